// round 4
// baseline (speedup 1.0000x reference)
#include <cuda_runtime.h>

#define N_NODES 100000
#define N_EDGES 1600000
#define FDIM 128
#define N_GRAPHS 256
#define NF4 (FDIM/4)
#define NODE_ELEMS (N_NODES*FDIM)

// -------- scratch (static device globals; no allocation anywhere) --------
__device__ int   g_indeg[N_NODES];
__device__ int   g_off[N_NODES];
__device__ int   g_cur[N_NODES];
__device__ int   g_csr[N_EDGES];       // src index per incoming edge, grouped by dst
__device__ float g_dinv[N_NODES];
__device__ float g_buf0[NODE_ELEMS];   // 51.2 MB
__device__ float g_buf1[NODE_ELEMS];   // 51.2 MB
__device__ float g_pool[N_GRAPHS*FDIM];
__device__ int   g_cnt[N_GRAPHS];

// -------- init --------
__global__ void k_init() {
    int i = blockIdx.x * blockDim.x + threadIdx.x;
    if (i < N_NODES) g_indeg[i] = 0;
    if (i < N_GRAPHS*FDIM) g_pool[i] = 0.0f;
    if (i < N_GRAPHS) g_cnt[i] = 0;
}

__global__ void k_degree(const int* __restrict__ ei) {
    int e = blockIdx.x * blockDim.x + threadIdx.x;
    if (e < N_EDGES) atomicAdd(&g_indeg[ei[N_EDGES + e]], 1);
}

// one-block exclusive scan over indegrees -> CSR offsets + fill cursors + dinv
__global__ void k_scan() {
    __shared__ int ssum[1024];
    int t = threadIdx.x;
    const int CH = (N_NODES + 1023) / 1024;      // 98
    int start = t * CH;
    int end   = start + CH; if (end > N_NODES) end = N_NODES;
    int s = 0;
    for (int i = start; i < end; i++) s += g_indeg[i];
    ssum[t] = s;
    __syncthreads();
    for (int off = 1; off < 1024; off <<= 1) {
        int v = (t >= off) ? ssum[t - off] : 0;
        __syncthreads();
        ssum[t] += v;
        __syncthreads();
    }
    int excl = ssum[t] - s;
    for (int i = start; i < end; i++) {
        g_off[i] = excl;
        g_cur[i] = excl;
        g_dinv[i] = rsqrtf((float)(g_indeg[i] + 1));   // +1 self loop
        excl += g_indeg[i];
    }
}

__global__ void k_fill(const int* __restrict__ ei) {
    int e = blockIdx.x * blockDim.x + threadIdx.x;
    if (e >= N_EDGES) return;
    int src = ei[e];
    int dst = ei[N_EDGES + e];
    int pos = atomicAdd(&g_cur[dst], 1);
    g_csr[pos] = src;
}

// g0 = dinv * x
__global__ void k_scale0(const float* __restrict__ x) {
    int i = blockIdx.x * blockDim.x + threadIdx.x;
    if (i >= N_NODES * NF4) return;
    float d = g_dinv[i / NF4];
    float4 t = ((const float4*)x)[i];
    t.x *= d; t.y *= d; t.z *= d; t.w *= d;
    ((float4*)g_buf0)[i] = t;
}

// one warp per dst node: out[dst] = scale * (sum_in in[src] + in[dst]); no atomics
// dir=0: buf0 -> buf1, scale = dinv^2 (hop 1, pre-scaled for hop 2)
// dir=1: buf1 -> buf0, scale = dinv   (hop 2, final h2)
__global__ void k_hop(int dir) {
    int w = (blockIdx.x * blockDim.x + threadIdx.x) >> 5;
    if (w >= N_NODES) return;
    int lane = threadIdx.x & 31;
    const float* in  = dir ? g_buf1 : g_buf0;
    float*       out = dir ? g_buf0 : g_buf1;
    float4 acc = *(const float4*)(in + (size_t)w * FDIM + lane * 4);  // self loop
    int beg = g_off[w];
    int cnt = g_indeg[w];
    int i = 0;
    for (; i + 4 <= cnt; i += 4) {      // 4-deep prefetch to expose MLP
        int s0 = __ldg(&g_csr[beg + i]);
        int s1 = __ldg(&g_csr[beg + i + 1]);
        int s2 = __ldg(&g_csr[beg + i + 2]);
        int s3 = __ldg(&g_csr[beg + i + 3]);
        float4 v0 = *(const float4*)(in + (size_t)s0 * FDIM + lane * 4);
        float4 v1 = *(const float4*)(in + (size_t)s1 * FDIM + lane * 4);
        float4 v2 = *(const float4*)(in + (size_t)s2 * FDIM + lane * 4);
        float4 v3 = *(const float4*)(in + (size_t)s3 * FDIM + lane * 4);
        acc.x += (v0.x + v1.x) + (v2.x + v3.x);
        acc.y += (v0.y + v1.y) + (v2.y + v3.y);
        acc.z += (v0.z + v1.z) + (v2.z + v3.z);
        acc.w += (v0.w + v1.w) + (v2.w + v3.w);
    }
    for (; i < cnt; i++) {
        int s0 = __ldg(&g_csr[beg + i]);
        float4 v0 = *(const float4*)(in + (size_t)s0 * FDIM + lane * 4);
        acc.x += v0.x; acc.y += v0.y; acc.z += v0.z; acc.w += v0.w;
    }
    float d = g_dinv[w];
    float f = dir ? d : d * d;
    acc.x *= f; acc.y *= f; acc.z *= f; acc.w *= f;
    *(float4*)(out + (size_t)w * FDIM + lane * 4) = acc;
}

__global__ void k_cnt(const int* __restrict__ batch) {
    int v = blockIdx.x * blockDim.x + threadIdx.x;
    if (v < N_NODES) atomicAdd(&g_cnt[batch[v]], 1);
}

// -------- fused: z = relu(h2@W + b) ; pool += z (segment-aggregated atomics) --------
#define NPB 64  // nodes per block
#define NPW 8   // nodes per warp
#define GEMM_SMEM ((FDIM*FDIM + NPB*FDIM)*4 + NPB*4)

__global__ __launch_bounds__(256, 1) void k_gemm_pool(
        const float* __restrict__ Wm, const float* __restrict__ bias,
        const int* __restrict__ batch) {
    extern __shared__ float smem[];
    float* sW = smem;                       // 64 KB
    float* sH = smem + FDIM*FDIM;           // 32 KB
    int*   sB = (int*)(sH + NPB*FDIM);
    int tid = threadIdx.x;

    for (int i = tid; i < FDIM*FDIM/4; i += 256)
        ((float4*)sW)[i] = ((const float4*)Wm)[i];

    int base = blockIdx.x * NPB;
    for (int i = tid; i < NPB*NF4; i += 256) {
        int n = i / NF4;
        int node = base + n;
        float4 t = make_float4(0.f, 0.f, 0.f, 0.f);
        if (node < N_NODES)
            t = ((const float4*)g_buf0)[node*NF4 + (i - n*NF4)];
        ((float4*)sH)[i] = t;
    }
    if (tid < NPB) {
        int node = base + tid;
        sB[tid] = (node < N_NODES) ? batch[node] : -1;
    }
    __syncthreads();

    int warp = tid >> 5, lane = tid & 31;
    int n0 = warp * NPW;
    float4 acc[NPW];
    #pragma unroll
    for (int n = 0; n < NPW; n++) acc[n] = make_float4(0.f, 0.f, 0.f, 0.f);

    // out[n][c] = sum_f h[n][f]*W[f][c]; lane owns cols 4*lane..4*lane+3
    for (int f = 0; f < FDIM; f += 4) {
        float4 w0 = *(const float4*)&sW[(f+0)*FDIM + lane*4];
        float4 w1 = *(const float4*)&sW[(f+1)*FDIM + lane*4];
        float4 w2 = *(const float4*)&sW[(f+2)*FDIM + lane*4];
        float4 w3 = *(const float4*)&sW[(f+3)*FDIM + lane*4];
        #pragma unroll
        for (int n = 0; n < NPW; n++) {
            float4 h = *(const float4*)&sH[(n0+n)*FDIM + f];  // warp-uniform broadcast
            acc[n].x += h.x*w0.x + h.y*w1.x + h.z*w2.x + h.w*w3.x;
            acc[n].y += h.x*w0.y + h.y*w1.y + h.z*w2.y + h.w*w3.y;
            acc[n].z += h.x*w0.z + h.y*w1.z + h.z*w2.z + h.w*w3.z;
            acc[n].w += h.x*w0.w + h.y*w1.w + h.z*w2.w + h.w*w3.w;
        }
    }

    float4 bv = *(const float4*)&bias[lane*4];
    // batch is sorted -> aggregate runs of equal graph id, flush once per run
    float4 run = make_float4(0.f, 0.f, 0.f, 0.f);
    int cur_gid = -1;
    #pragma unroll
    for (int n = 0; n < NPW; n++) {
        int gid = sB[n0+n];
        float4 r;
        r.x = fmaxf(acc[n].x + bv.x, 0.0f);
        r.y = fmaxf(acc[n].y + bv.y, 0.0f);
        r.z = fmaxf(acc[n].z + bv.z, 0.0f);
        r.w = fmaxf(acc[n].w + bv.w, 0.0f);
        if (gid != cur_gid) {
            if (cur_gid >= 0) {
                float* p = g_pool + cur_gid*FDIM + lane*4;
                atomicAdd(p+0, run.x); atomicAdd(p+1, run.y);
                atomicAdd(p+2, run.z); atomicAdd(p+3, run.w);
            }
            cur_gid = gid;
            run = r;
        } else {
            run.x += r.x; run.y += r.y; run.z += r.z; run.w += r.w;
        }
    }
    if (cur_gid >= 0) {
        float* p = g_pool + cur_gid*FDIM + lane*4;
        atomicAdd(p+0, run.x); atomicAdd(p+1, run.y);
        atomicAdd(p+2, run.z); atomicAdd(p+3, run.w);
    }
}

// -------- mean + log_softmax, one block (128 threads) per graph --------
__global__ void k_softmax(float* __restrict__ out) {
    int g = blockIdx.x;
    int t = threadIdx.x;
    __shared__ float sm[4], ss[4];
    float c = fmaxf((float)g_cnt[g], 1.0f);
    float v = g_pool[g*FDIM + t] / c;
    float m = v;
    #pragma unroll
    for (int o = 16; o; o >>= 1) m = fmaxf(m, __shfl_xor_sync(0xffffffffu, m, o));
    if ((t & 31) == 0) sm[t >> 5] = m;
    __syncthreads();
    m = fmaxf(fmaxf(sm[0], sm[1]), fmaxf(sm[2], sm[3]));
    float e = expf(v - m);
    float s = e;
    #pragma unroll
    for (int o = 16; o; o >>= 1) s += __shfl_xor_sync(0xffffffffu, s, o);
    if ((t & 31) == 0) ss[t >> 5] = s;
    __syncthreads();
    s = ss[0] + ss[1] + ss[2] + ss[3];
    out[g*FDIM + t] = v - m - logf(s);
}

extern "C" void kernel_launch(void* const* d_in, const int* in_sizes, int n_in,
                              void* d_out, int out_size) {
    const float* x     = (const float*)d_in[0];
    const int*   ei    = (const int*)d_in[1];     // int32 (JAX x64 disabled)
    const int*   batch = (const int*)d_in[2];     // int32
    const float* Wm    = (const float*)d_in[3];
    const float* bias  = (const float*)d_in[4];
    float*       out   = (float*)d_out;

    cudaFuncSetAttribute(k_gemm_pool, cudaFuncAttributeMaxDynamicSharedMemorySize, GEMM_SMEM);

    k_init   <<<(N_NODES + 255) / 256, 256>>>();
    k_degree <<<(N_EDGES + 255) / 256, 256>>>(ei);
    k_scan   <<<1, 1024>>>();
    k_fill   <<<(N_EDGES + 255) / 256, 256>>>(ei);
    k_scale0 <<<(N_NODES * NF4 + 255) / 256, 256>>>(x);
    k_hop    <<<(N_NODES * 32 + 255) / 256, 256>>>(0);  // hop 1: buf0 -> buf1
    k_hop    <<<(N_NODES * 32 + 255) / 256, 256>>>(1);  // hop 2: buf1 -> buf0
    k_cnt    <<<(N_NODES + 255) / 256, 256>>>(batch);
    k_gemm_pool<<<(N_NODES + NPB - 1) / NPB, 256, GEMM_SMEM>>>(Wm, bias, batch);
    k_softmax<<<N_GRAPHS, FDIM>>>(out);
}

// round 5
// speedup vs baseline: 1.9041x; 1.9041x over previous
#include <cuda_runtime.h>
#include <cuda_fp16.h>

#define N_NODES 100000
#define N_EDGES 1600000
#define FDIM 128
#define N_GRAPHS 256
#define NF4 (FDIM/4)
#define NODE_ELEMS (N_NODES*FDIM)
#define NQ (NODE_ELEMS/4)          // uint2 (4 halfs) count
#define SCAN_B 1024
#define NBLK ((N_NODES + SCAN_B - 1)/SCAN_B)   // 98

// -------- scratch (static device globals; no allocation anywhere) --------
__device__ int   g_indeg[N_NODES];
__device__ int   g_off[N_NODES];
__device__ int   g_cur[N_NODES];
__device__ int   g_csr[N_EDGES];
__device__ float g_dinv[N_NODES];
__device__ int   g_bsum[NBLK];
__device__ int   g_boff[NBLK];
__device__ uint2 g_h0[NQ];          // 25.6 MB fp16 features
__device__ uint2 g_h1[NQ];          // 25.6 MB fp16 features
__device__ float g_pool[N_GRAPHS*FDIM];
__device__ int   g_cnt[N_GRAPHS];

__device__ __forceinline__ float4 h4_to_f4(uint2 u) {
    __half2 a = *(__half2*)&u.x;
    __half2 b = *(__half2*)&u.y;
    float2 fa = __half22float2(a);
    float2 fb = __half22float2(b);
    return make_float4(fa.x, fa.y, fb.x, fb.y);
}
__device__ __forceinline__ uint2 f4_to_h4(float4 v) {
    __half2 a = __floats2half2_rn(v.x, v.y);
    __half2 b = __floats2half2_rn(v.z, v.w);
    uint2 u;
    u.x = *(unsigned*)&a;
    u.y = *(unsigned*)&b;
    return u;
}

// -------- init --------
__global__ void k_init() {
    int i = blockIdx.x * blockDim.x + threadIdx.x;
    if (i < N_NODES) g_indeg[i] = 0;
    if (i < N_GRAPHS*FDIM) g_pool[i] = 0.0f;
    if (i < N_GRAPHS) g_cnt[i] = 0;
}

__global__ void k_degree(const int* __restrict__ ei) {
    int e = blockIdx.x * blockDim.x + threadIdx.x;
    if (e < N_EDGES) atomicAdd(&g_indeg[ei[N_EDGES + e]], 1);
}

// -------- 3-phase coalesced exclusive scan of indegrees --------
__global__ void k_scan1() {
    __shared__ int sh[32];
    int b = blockIdx.x, t = threadIdx.x;
    int i = b * SCAN_B + t;
    int v = (i < N_NODES) ? g_indeg[i] : 0;
    #pragma unroll
    for (int o = 16; o; o >>= 1) v += __shfl_xor_sync(0xffffffffu, v, o);
    if ((t & 31) == 0) sh[t >> 5] = v;
    __syncthreads();
    if (t < 32) {
        int s = sh[t];
        #pragma unroll
        for (int o = 16; o; o >>= 1) s += __shfl_xor_sync(0xffffffffu, s, o);
        if (t == 0) g_bsum[b] = s;
    }
}

__global__ void k_scan2() {
    if (threadIdx.x == 0) {
        int acc = 0;
        for (int b = 0; b < NBLK; b++) { g_boff[b] = acc; acc += g_bsum[b]; }
    }
}

__global__ void k_scan3() {
    __shared__ int wsum[32];
    int b = blockIdx.x, t = threadIdx.x;
    int i = b * SCAN_B + t;
    int v = (i < N_NODES) ? g_indeg[i] : 0;
    int xs = v;
    #pragma unroll
    for (int o = 1; o < 32; o <<= 1) {
        int y = __shfl_up_sync(0xffffffffu, xs, o);
        if ((t & 31) >= o) xs += y;
    }
    if ((t & 31) == 31) wsum[t >> 5] = xs;
    __syncthreads();
    if (t < 32) {
        int s = wsum[t];
        #pragma unroll
        for (int o = 1; o < 32; o <<= 1) {
            int y = __shfl_up_sync(0xffffffffu, s, o);
            if (t >= o) s += y;
        }
        wsum[t] = s;   // inclusive over warps
    }
    __syncthreads();
    int base = g_boff[b] + ((t >= 32) ? wsum[(t >> 5) - 1] : 0);
    int excl = base + xs - v;
    if (i < N_NODES) {
        g_off[i] = excl;
        g_cur[i] = excl;
        g_dinv[i] = rsqrtf((float)(v + 1));
    }
}

__global__ void k_fill(const int* __restrict__ ei) {
    int e = blockIdx.x * blockDim.x + threadIdx.x;
    if (e >= N_EDGES) return;
    int src = ei[e];
    int dst = ei[N_EDGES + e];
    int pos = atomicAdd(&g_cur[dst], 1);
    g_csr[pos] = src;
}

// h0 = fp16(dinv * x)
__global__ void k_cvt(const float* __restrict__ x) {
    int i = blockIdx.x * blockDim.x + threadIdx.x;
    if (i >= NQ) return;
    float d = g_dinv[i >> 5];
    float4 t = ((const float4*)x)[i];
    t.x *= d; t.y *= d; t.z *= d; t.w *= d;
    g_h0[i] = f4_to_h4(t);
}

// one warp per dst node: out[dst] = scale * (sum_in in[src] + in[dst]); fp32 accum
// dir=0: h0 -> h1, scale = dinv^2 (hop 1, pre-scaled for hop 2)
// dir=1: h1 -> h0, scale = dinv   (hop 2, final h2)
__global__ void k_hop(int dir) {
    int w = (blockIdx.x * blockDim.x + threadIdx.x) >> 5;
    if (w >= N_NODES) return;
    int lane = threadIdx.x & 31;
    const uint2* in  = dir ? g_h1 : g_h0;
    uint2*       out = dir ? g_h0 : g_h1;
    int idx = w * 32 + lane;
    float4 acc = h4_to_f4(__ldg(&in[idx]));     // self loop
    int beg = g_off[w];
    int cnt = g_indeg[w];
    int i = 0;
    for (; i + 4 <= cnt; i += 4) {
        int s0 = __ldg(&g_csr[beg + i]);
        int s1 = __ldg(&g_csr[beg + i + 1]);
        int s2 = __ldg(&g_csr[beg + i + 2]);
        int s3 = __ldg(&g_csr[beg + i + 3]);
        uint2 u0 = __ldg(&in[s0 * 32 + lane]);
        uint2 u1 = __ldg(&in[s1 * 32 + lane]);
        uint2 u2 = __ldg(&in[s2 * 32 + lane]);
        uint2 u3 = __ldg(&in[s3 * 32 + lane]);
        float4 v0 = h4_to_f4(u0), v1 = h4_to_f4(u1);
        float4 v2 = h4_to_f4(u2), v3 = h4_to_f4(u3);
        acc.x += (v0.x + v1.x) + (v2.x + v3.x);
        acc.y += (v0.y + v1.y) + (v2.y + v3.y);
        acc.z += (v0.z + v1.z) + (v2.z + v3.z);
        acc.w += (v0.w + v1.w) + (v2.w + v3.w);
    }
    for (; i < cnt; i++) {
        int s0 = __ldg(&g_csr[beg + i]);
        float4 v0 = h4_to_f4(__ldg(&in[s0 * 32 + lane]));
        acc.x += v0.x; acc.y += v0.y; acc.z += v0.z; acc.w += v0.w;
    }
    float d = g_dinv[w];
    float f = dir ? d : d * d;
    acc.x *= f; acc.y *= f; acc.z *= f; acc.w *= f;
    out[idx] = f4_to_h4(acc);
}

__global__ void k_cnt(const int* __restrict__ batch) {
    int v = blockIdx.x * blockDim.x + threadIdx.x;
    if (v < N_NODES) atomicAdd(&g_cnt[batch[v]], 1);
}

// -------- fused: z = relu(h2@W + b) ; pool += z (segment-aggregated atomics) --------
#define NPB 64
#define NPW 8
#define GEMM_SMEM ((FDIM*FDIM + NPB*FDIM)*4 + NPB*4)

__global__ __launch_bounds__(256, 1) void k_gemm_pool(
        const float* __restrict__ Wm, const float* __restrict__ bias,
        const int* __restrict__ batch) {
    extern __shared__ float smem[];
    float* sW = smem;                       // 64 KB
    float* sH = smem + FDIM*FDIM;           // 32 KB
    int*   sB = (int*)(sH + NPB*FDIM);
    int tid = threadIdx.x;

    for (int i = tid; i < FDIM*FDIM/4; i += 256)
        ((float4*)sW)[i] = ((const float4*)Wm)[i];

    int base = blockIdx.x * NPB;
    for (int i = tid; i < NPB*32; i += 256) {
        int node = base + (i >> 5);
        float4 t = make_float4(0.f, 0.f, 0.f, 0.f);
        if (node < N_NODES)
            t = h4_to_f4(g_h0[node * 32 + (i & 31)]);
        ((float4*)sH)[i] = t;
    }
    if (tid < NPB) {
        int node = base + tid;
        sB[tid] = (node < N_NODES) ? batch[node] : -1;
    }
    __syncthreads();

    int warp = tid >> 5, lane = tid & 31;
    int n0 = warp * NPW;
    float4 acc[NPW];
    #pragma unroll
    for (int n = 0; n < NPW; n++) acc[n] = make_float4(0.f, 0.f, 0.f, 0.f);

    for (int f = 0; f < FDIM; f += 4) {
        float4 w0 = *(const float4*)&sW[(f+0)*FDIM + lane*4];
        float4 w1 = *(const float4*)&sW[(f+1)*FDIM + lane*4];
        float4 w2 = *(const float4*)&sW[(f+2)*FDIM + lane*4];
        float4 w3 = *(const float4*)&sW[(f+3)*FDIM + lane*4];
        #pragma unroll
        for (int n = 0; n < NPW; n++) {
            float4 h = *(const float4*)&sH[(n0+n)*FDIM + f];
            acc[n].x += h.x*w0.x + h.y*w1.x + h.z*w2.x + h.w*w3.x;
            acc[n].y += h.x*w0.y + h.y*w1.y + h.z*w2.y + h.w*w3.y;
            acc[n].z += h.x*w0.z + h.y*w1.z + h.z*w2.z + h.w*w3.z;
            acc[n].w += h.x*w0.w + h.y*w1.w + h.z*w2.w + h.w*w3.w;
        }
    }

    float4 bv = *(const float4*)&bias[lane*4];
    float4 run = make_float4(0.f, 0.f, 0.f, 0.f);
    int cur_gid = -1;
    #pragma unroll
    for (int n = 0; n < NPW; n++) {
        int gid = sB[n0+n];
        float4 r;
        r.x = fmaxf(acc[n].x + bv.x, 0.0f);
        r.y = fmaxf(acc[n].y + bv.y, 0.0f);
        r.z = fmaxf(acc[n].z + bv.z, 0.0f);
        r.w = fmaxf(acc[n].w + bv.w, 0.0f);
        if (gid != cur_gid) {
            if (cur_gid >= 0) {
                float* p = g_pool + cur_gid*FDIM + lane*4;
                atomicAdd(p+0, run.x); atomicAdd(p+1, run.y);
                atomicAdd(p+2, run.z); atomicAdd(p+3, run.w);
            }
            cur_gid = gid;
            run = r;
        } else {
            run.x += r.x; run.y += r.y; run.z += r.z; run.w += r.w;
        }
    }
    if (cur_gid >= 0) {
        float* p = g_pool + cur_gid*FDIM + lane*4;
        atomicAdd(p+0, run.x); atomicAdd(p+1, run.y);
        atomicAdd(p+2, run.z); atomicAdd(p+3, run.w);
    }
}

// -------- mean + log_softmax, one block (128 threads) per graph --------
__global__ void k_softmax(float* __restrict__ out) {
    int g = blockIdx.x;
    int t = threadIdx.x;
    __shared__ float sm[4], ss[4];
    float c = fmaxf((float)g_cnt[g], 1.0f);
    float v = g_pool[g*FDIM + t] / c;
    float m = v;
    #pragma unroll
    for (int o = 16; o; o >>= 1) m = fmaxf(m, __shfl_xor_sync(0xffffffffu, m, o));
    if ((t & 31) == 0) sm[t >> 5] = m;
    __syncthreads();
    m = fmaxf(fmaxf(sm[0], sm[1]), fmaxf(sm[2], sm[3]));
    float e = expf(v - m);
    float s = e;
    #pragma unroll
    for (int o = 16; o; o >>= 1) s += __shfl_xor_sync(0xffffffffu, s, o);
    if ((t & 31) == 0) ss[t >> 5] = s;
    __syncthreads();
    s = ss[0] + ss[1] + ss[2] + ss[3];
    out[g*FDIM + t] = v - m - logf(s);
}

extern "C" void kernel_launch(void* const* d_in, const int* in_sizes, int n_in,
                              void* d_out, int out_size) {
    const float* x     = (const float*)d_in[0];
    const int*   ei    = (const int*)d_in[1];
    const int*   batch = (const int*)d_in[2];
    const float* Wm    = (const float*)d_in[3];
    const float* bias  = (const float*)d_in[4];
    float*       out   = (float*)d_out;

    cudaFuncSetAttribute(k_gemm_pool, cudaFuncAttributeMaxDynamicSharedMemorySize, GEMM_SMEM);

    k_init   <<<(N_NODES + 255) / 256, 256>>>();
    k_degree <<<(N_EDGES + 255) / 256, 256>>>(ei);
    k_scan1  <<<NBLK, SCAN_B>>>();
    k_scan2  <<<1, 32>>>();
    k_scan3  <<<NBLK, SCAN_B>>>();
    k_fill   <<<(N_EDGES + 255) / 256, 256>>>(ei);
    k_cvt    <<<(NQ + 255) / 256, 256>>>(x);
    k_hop    <<<(N_NODES * 32 + 255) / 256, 256>>>(0);  // hop 1: h0 -> h1
    k_hop    <<<(N_NODES * 32 + 255) / 256, 256>>>(1);  // hop 2: h1 -> h0
    k_cnt    <<<(N_NODES + 255) / 256, 256>>>(batch);
    k_gemm_pool<<<(N_NODES + NPB - 1) / NPB, 256, GEMM_SMEM>>>(Wm, bias, batch);
    k_softmax<<<N_GRAPHS, FDIM>>>(out);
}

// round 8
// speedup vs baseline: 2.7059x; 1.4211x over previous
#include <cuda_runtime.h>
#include <cuda_fp16.h>

#define N_NODES 100000
#define N_EDGES 1600000
#define FDIM 128
#define N_GRAPHS 256
#define NODE_ELEMS (N_NODES*FDIM)
#define NQ (NODE_ELEMS/4)          // uint2 (4 halfs) count
#define SCAN_B 1024
#define NBLK ((N_NODES + SCAN_B - 1)/SCAN_B)   // 98

// -------- scratch (static device globals; no allocation anywhere) --------
__device__ int    g_indeg[N_NODES];
__device__ int    g_off[N_NODES];
__device__ int    g_cur[N_NODES];
__device__ int    g_csr[N_EDGES];
__device__ float  g_dinv[N_NODES];
__device__ int    g_bsum[NBLK];
__device__ uint2  g_h0[NQ];         // 25.6 MB fp16 features
__device__ uint2  g_h1[NQ];         // 25.6 MB fp16 features
__device__ __half g_Wh[FDIM*FDIM];  // W^T in fp16: g_Wh[c*128+f] = W[f][c]
__device__ float  g_pool[N_GRAPHS*FDIM];
__device__ int    g_cnt[N_GRAPHS];

__device__ __forceinline__ float4 h4_to_f4(uint2 u) {
    __half2 a = *(__half2*)&u.x;
    __half2 b = *(__half2*)&u.y;
    float2 fa = __half22float2(a);
    float2 fb = __half22float2(b);
    return make_float4(fa.x, fa.y, fb.x, fb.y);
}
__device__ __forceinline__ uint2 f4_to_h4(float4 v) {
    __half2 a = __floats2half2_rn(v.x, v.y);
    __half2 b = __floats2half2_rn(v.z, v.w);
    uint2 u;
    u.x = *(unsigned*)&a;
    u.y = *(unsigned*)&b;
    return u;
}

// -------- init --------
__global__ void k_init() {
    int i = blockIdx.x * blockDim.x + threadIdx.x;
    if (i < N_NODES) g_indeg[i] = 0;
    if (i < N_GRAPHS*FDIM) g_pool[i] = 0.0f;
    if (i < N_GRAPHS) g_cnt[i] = 0;
}

__global__ void k_degree(const int* __restrict__ ei) {
    int e = blockIdx.x * blockDim.x + threadIdx.x;
    if (e < N_EDGES) atomicAdd(&g_indeg[ei[N_EDGES + e]], 1);
}

// W fp32 [f][c] -> fp16 transposed [c][f]
__global__ void k_wcvt(const float* __restrict__ Wm) {
    int i = blockIdx.x * blockDim.x + threadIdx.x;   // i = f*128 + c
    if (i >= FDIM*FDIM) return;
    int f = i >> 7, c = i & 127;
    g_Wh[c*FDIM + f] = __float2half(Wm[i]);
}

// -------- 2-phase coalesced exclusive scan of indegrees --------
__global__ void k_scan1() {
    __shared__ int sh[32];
    int b = blockIdx.x, t = threadIdx.x;
    int i = b * SCAN_B + t;
    int v = (i < N_NODES) ? g_indeg[i] : 0;
    #pragma unroll
    for (int o = 16; o; o >>= 1) v += __shfl_xor_sync(0xffffffffu, v, o);
    if ((t & 31) == 0) sh[t >> 5] = v;
    __syncthreads();
    if (t < 32) {
        int s = sh[t];
        #pragma unroll
        for (int o = 16; o; o >>= 1) s += __shfl_xor_sync(0xffffffffu, s, o);
        if (t == 0) g_bsum[b] = s;
    }
}

// block-local scan; warp 0 sums prior block-sums in parallel (no scan2 kernel)
__global__ void k_scan3() {
    __shared__ int wsum[32];
    __shared__ int sboff;
    int b = blockIdx.x, t = threadIdx.x;
    if (t < 32) {
        int acc = 0;
        for (int j = t; j < b; j += 32) acc += g_bsum[j];
        #pragma unroll
        for (int o = 16; o; o >>= 1) acc += __shfl_xor_sync(0xffffffffu, acc, o);
        if (t == 0) sboff = acc;
    }
    int i = b * SCAN_B + t;
    int v = (i < N_NODES) ? g_indeg[i] : 0;
    int xs = v;
    #pragma unroll
    for (int o = 1; o < 32; o <<= 1) {
        int y = __shfl_up_sync(0xffffffffu, xs, o);
        if ((t & 31) >= o) xs += y;
    }
    if ((t & 31) == 31) wsum[t >> 5] = xs;
    __syncthreads();
    if (t < 32) {
        int s = wsum[t];
        #pragma unroll
        for (int o = 1; o < 32; o <<= 1) {
            int y = __shfl_up_sync(0xffffffffu, s, o);
            if (t >= o) s += y;
        }
        wsum[t] = s;   // inclusive over warps
    }
    __syncthreads();
    int base = sboff + ((t >= 32) ? wsum[(t >> 5) - 1] : 0);
    int excl = base + xs - v;
    if (i < N_NODES) {
        g_off[i] = excl;
        g_cur[i] = excl;
        g_dinv[i] = rsqrtf((float)(v + 1));
    }
}

__global__ void k_fill(const int* __restrict__ ei) {
    int e = blockIdx.x * blockDim.x + threadIdx.x;
    if (e >= N_EDGES) return;
    int src = ei[e];
    int dst = ei[N_EDGES + e];
    int pos = atomicAdd(&g_cur[dst], 1);
    g_csr[pos] = src;
}

// h0 = fp16(dinv * x)
__global__ void k_cvt(const float* __restrict__ x) {
    int i = blockIdx.x * blockDim.x + threadIdx.x;
    if (i >= NQ) return;
    float d = g_dinv[i >> 5];
    float4 t = ((const float4*)x)[i];
    t.x *= d; t.y *= d; t.z *= d; t.w *= d;
    g_h0[i] = f4_to_h4(t);
}

// one warp per dst node; fp32 accum; 8-deep unrolled gather
__global__ void k_hop(int dir) {
    int w = (blockIdx.x * blockDim.x + threadIdx.x) >> 5;
    if (w >= N_NODES) return;
    int lane = threadIdx.x & 31;
    const uint2* in  = dir ? g_h1 : g_h0;
    uint2*       out = dir ? g_h0 : g_h1;
    int idx = w * 32 + lane;
    float4 acc = h4_to_f4(__ldg(&in[idx]));     // self loop
    int beg = g_off[w];
    int cnt = g_indeg[w];
    int i = 0;
    for (; i + 8 <= cnt; i += 8) {
        int s[8];
        #pragma unroll
        for (int j = 0; j < 8; j++) s[j] = __ldg(&g_csr[beg + i + j]);
        uint2 u[8];
        #pragma unroll
        for (int j = 0; j < 8; j++) u[j] = __ldg(&in[s[j] * 32 + lane]);
        #pragma unroll
        for (int j = 0; j < 8; j++) {
            float4 v = h4_to_f4(u[j]);
            acc.x += v.x; acc.y += v.y; acc.z += v.z; acc.w += v.w;
        }
    }
    for (; i < cnt; i++) {
        int s0 = __ldg(&g_csr[beg + i]);
        float4 v0 = h4_to_f4(__ldg(&in[s0 * 32 + lane]));
        acc.x += v0.x; acc.y += v0.y; acc.z += v0.z; acc.w += v0.w;
    }
    float d = g_dinv[w];
    float f = dir ? d : d * d;
    acc.x *= f; acc.y *= f; acc.z *= f; acc.w *= f;
    out[idx] = f4_to_h4(acc);
}

__global__ void k_cnt(const int* __restrict__ batch) {
    int v = blockIdx.x * blockDim.x + threadIdx.x;
    if (v < N_NODES) atomicAdd(&g_cnt[batch[v]], 1);
}

// -------- tensor-core GEMM + pool: z = relu(h2@W + b); pool += z --------
// block = 128 threads (4 warps), 64 nodes per block, full N=128.
// sA [64][136] fp16 (17408 B), sW [128][136] fp16 (34816 B), overlay sOut [64][128] f32.
#define GM_NODES 64
#define SAS 136
#define SWS 136
#define SMEM_A_BYTES (GM_NODES*SAS*2)
#define SMEM_W_BYTES (FDIM*SWS*2)
#define GEMM_SMEM (SMEM_A_BYTES + SMEM_W_BYTES + GM_NODES*4)

__device__ __forceinline__ void mma16816(float4& d, unsigned a0, unsigned a1,
                                         unsigned a2, unsigned a3,
                                         unsigned b0, unsigned b1) {
    asm volatile("mma.sync.aligned.m16n8k16.row.col.f32.f16.f16.f32 "
        "{%0,%1,%2,%3}, {%4,%5,%6,%7}, {%8,%9}, {%0,%1,%2,%3};"
        : "+f"(d.x), "+f"(d.y), "+f"(d.z), "+f"(d.w)
        : "r"(a0), "r"(a1), "r"(a2), "r"(a3), "r"(b0), "r"(b1));
}

__global__ __launch_bounds__(128, 2) void k_gemm_pool(
        const float* __restrict__ bias, const int* __restrict__ batch) {
    extern __shared__ char smem[];
    __half* sA = (__half*)smem;                       // [64][SAS]
    __half* sW = (__half*)(smem + SMEM_A_BYTES);      // [128][SWS] (W^T: [n][k])
    float*  sO = (float*)smem;                        // overlay [64][128]
    int*    sB = (int*)(smem + SMEM_A_BYTES + SMEM_W_BYTES);
    int tid = threadIdx.x;
    int base = blockIdx.x * GM_NODES;

    // load A: 64 nodes x 32 uint2
    for (int i = tid; i < GM_NODES*32; i += 128) {
        int r = i >> 5, q = i & 31;
        int node = base + r;
        uint2 u = make_uint2(0u, 0u);
        if (node < N_NODES) u = g_h0[node*32 + q];
        *(uint2*)&sA[r*SAS + q*4] = u;
    }
    // load W^T: 128 rows x 32 uint2
    for (int i = tid; i < FDIM*32; i += 128) {
        int r = i >> 5, q = i & 31;
        uint2 u = *(const uint2*)&g_Wh[r*FDIM + q*4];
        *(uint2*)&sW[r*SWS + q*4] = u;
    }
    if (tid < GM_NODES) {
        int node = base + tid;
        sB[tid] = (node < N_NODES) ? batch[node] : -1;
    }
    __syncthreads();

    int warp = tid >> 5, lane = tid & 31;
    int gid = lane >> 2, tig = lane & 3;
    int m0 = warp * 16;

    float4 acc[16];
    #pragma unroll
    for (int t = 0; t < 16; t++) acc[t] = make_float4(0.f, 0.f, 0.f, 0.f);

    #pragma unroll
    for (int k0 = 0; k0 < FDIM; k0 += 16) {
        unsigned a0 = *(unsigned*)&sA[(m0+gid)  *SAS + k0 + tig*2];
        unsigned a1 = *(unsigned*)&sA[(m0+gid+8)*SAS + k0 + tig*2];
        unsigned a2 = *(unsigned*)&sA[(m0+gid)  *SAS + k0 + tig*2 + 8];
        unsigned a3 = *(unsigned*)&sA[(m0+gid+8)*SAS + k0 + tig*2 + 8];
        #pragma unroll
        for (int t = 0; t < 16; t++) {
            int n0 = t * 8;
            unsigned b0 = *(unsigned*)&sW[(n0+gid)*SWS + k0 + tig*2];
            unsigned b1 = *(unsigned*)&sW[(n0+gid)*SWS + k0 + tig*2 + 8];
            mma16816(acc[t], a0, a1, a2, a3, b0, b1);
        }
    }

    __syncthreads();   // all A/W reads done before overlay writes
    #pragma unroll
    for (int t = 0; t < 16; t++) {
        int n0 = t * 8;
        sO[(m0+gid)  *FDIM + n0 + tig*2]     = acc[t].x;
        sO[(m0+gid)  *FDIM + n0 + tig*2 + 1] = acc[t].y;
        sO[(m0+gid+8)*FDIM + n0 + tig*2]     = acc[t].z;
        sO[(m0+gid+8)*FDIM + n0 + tig*2 + 1] = acc[t].w;
    }
    __syncwarp();      // each warp reads only its own 16 rows

    float4 bv = *(const float4*)&bias[lane*4];
    float4 run = make_float4(0.f, 0.f, 0.f, 0.f);
    int cur_gid = -1;
    #pragma unroll
    for (int n = 0; n < 16; n++) {
        int row = m0 + n;
        int gidn = sB[row];
        float4 a = *(float4*)&sO[row*FDIM + lane*4];
        float4 r;
        r.x = fmaxf(a.x + bv.x, 0.0f);
        r.y = fmaxf(a.y + bv.y, 0.0f);
        r.z = fmaxf(a.z + bv.z, 0.0f);
        r.w = fmaxf(a.w + bv.w, 0.0f);
        if (gidn != cur_gid) {
            if (cur_gid >= 0) {
                float* p = g_pool + cur_gid*FDIM + lane*4;
                atomicAdd(p+0, run.x); atomicAdd(p+1, run.y);
                atomicAdd(p+2, run.z); atomicAdd(p+3, run.w);
            }
            cur_gid = gidn;
            run = r;
        } else {
            run.x += r.x; run.y += r.y; run.z += r.z; run.w += r.w;
        }
    }
    if (cur_gid >= 0) {
        float* p = g_pool + cur_gid*FDIM + lane*4;
        atomicAdd(p+0, run.x); atomicAdd(p+1, run.y);
        atomicAdd(p+2, run.z); atomicAdd(p+3, run.w);
    }
}

// -------- mean + log_softmax, one block (128 threads) per graph --------
__global__ void k_softmax(float* __restrict__ out) {
    int g = blockIdx.x;
    int t = threadIdx.x;
    __shared__ float sm[4], ss[4];
    float c = fmaxf((float)g_cnt[g], 1.0f);
    float v = g_pool[g*FDIM + t] / c;
    float m = v;
    #pragma unroll
    for (int o = 16; o; o >>= 1) m = fmaxf(m, __shfl_xor_sync(0xffffffffu, m, o));
    if ((t & 31) == 0) sm[t >> 5] = m;
    __syncthreads();
    m = fmaxf(fmaxf(sm[0], sm[1]), fmaxf(sm[2], sm[3]));
    float e = expf(v - m);
    float s = e;
    #pragma unroll
    for (int o = 16; o; o >>= 1) s += __shfl_xor_sync(0xffffffffu, s, o);
    if ((t & 31) == 0) ss[t >> 5] = s;
    __syncthreads();
    s = ss[0] + ss[1] + ss[2] + ss[3];
    out[g*FDIM + t] = v - m - logf(s);
}

extern "C" void kernel_launch(void* const* d_in, const int* in_sizes, int n_in,
                              void* d_out, int out_size) {
    const float* x     = (const float*)d_in[0];
    const int*   ei    = (const int*)d_in[1];
    const int*   batch = (const int*)d_in[2];
    const float* Wm    = (const float*)d_in[3];
    const float* bias  = (const float*)d_in[4];
    float*       out   = (float*)d_out;

    cudaFuncSetAttribute(k_gemm_pool, cudaFuncAttributeMaxDynamicSharedMemorySize, GEMM_SMEM);

    k_init   <<<(N_NODES + 255) / 256, 256>>>();
    k_degree <<<(N_EDGES + 255) / 256, 256>>>(ei);
    k_wcvt   <<<(FDIM*FDIM + 255) / 256, 256>>>(Wm);
    k_scan1  <<<NBLK, SCAN_B>>>();
    k_scan3  <<<NBLK, SCAN_B>>>();
    k_fill   <<<(N_EDGES + 255) / 256, 256>>>(ei);
    k_cvt    <<<(NQ + 255) / 256, 256>>>(x);
    k_hop    <<<(N_NODES * 32 + 255) / 256, 256>>>(0);  // hop 1: h0 -> h1
    k_hop    <<<(N_NODES * 32 + 255) / 256, 256>>>(1);  // hop 2: h1 -> h0
    k_cnt    <<<(N_NODES + 255) / 256, 256>>>(batch);
    k_gemm_pool<<<(N_NODES + GM_NODES - 1) / GM_NODES, 128, GEMM_SMEM>>>(bias, batch);
    k_softmax<<<N_GRAPHS, FDIM>>>(out);
}

// round 11
// speedup vs baseline: 2.7626x; 1.0210x over previous
#include <cuda_runtime.h>
#include <cuda_fp16.h>

#define N_NODES 100000
#define N_EDGES 1600000
#define FDIM 128
#define N_GRAPHS 256
#define NODE_ELEMS (N_NODES*FDIM)
#define NQ (NODE_ELEMS/4)          // uint2 (4 halfs) count
#define SCAN_B 1024
#define NBLK ((N_NODES + SCAN_B - 1)/SCAN_B)   // 98

// -------- scratch (static device globals; no allocation anywhere) --------
__device__ int    g_indeg[N_NODES];
__device__ int    g_off[N_NODES];
__device__ int    g_cur[N_NODES];
__device__ int    g_csr[N_EDGES];
__device__ float  g_dinv[N_NODES];
__device__ int    g_bsum[NBLK];
__device__ uint2  g_h0[NQ];         // 25.6 MB fp16 features
__device__ uint2  g_h1[NQ];         // 25.6 MB fp16 features
__device__ __half g_Wh[FDIM*FDIM];  // W^T in fp16: g_Wh[c*128+f] = W[f][c]
__device__ float  g_pool[N_GRAPHS*FDIM];
__device__ int    g_cnt[N_GRAPHS];

__device__ __forceinline__ float4 h4_to_f4(uint2 u) {
    __half2 a = *(__half2*)&u.x;
    __half2 b = *(__half2*)&u.y;
    float2 fa = __half22float2(a);
    float2 fb = __half22float2(b);
    return make_float4(fa.x, fa.y, fb.x, fb.y);
}
__device__ __forceinline__ uint2 f4_to_h4(float4 v) {
    __half2 a = __floats2half2_rn(v.x, v.y);
    __half2 b = __floats2half2_rn(v.z, v.w);
    uint2 u;
    u.x = *(unsigned*)&a;
    u.y = *(unsigned*)&b;
    return u;
}

// -------- fused init + W convert --------
__global__ void k_init_wcvt(const float* __restrict__ Wm) {
    int i = blockIdx.x * blockDim.x + threadIdx.x;
    if (i < N_NODES) g_indeg[i] = 0;
    if (i < N_GRAPHS*FDIM) g_pool[i] = 0.0f;
    if (i < N_GRAPHS) g_cnt[i] = 0;
    if (i < FDIM*FDIM) {                 // W fp32 [f][c] -> fp16 transposed [c][f]
        int f = i >> 7, c = i & 127;
        g_Wh[c*FDIM + f] = __float2half(Wm[i]);
    }
}

// -------- degree histogram + per-graph node counts (folded) --------
__global__ void k_degree_cnt(const int* __restrict__ ei, const int* __restrict__ batch) {
    int e = blockIdx.x * blockDim.x + threadIdx.x;
    if (e < N_EDGES) atomicAdd(&g_indeg[ei[N_EDGES + e]], 1);
    if (e < N_NODES) atomicAdd(&g_cnt[batch[e]], 1);
}

// -------- 2-phase coalesced exclusive scan of indegrees --------
__global__ void k_scan1() {
    __shared__ int sh[32];
    int b = blockIdx.x, t = threadIdx.x;
    int i = b * SCAN_B + t;
    int v = (i < N_NODES) ? g_indeg[i] : 0;
    #pragma unroll
    for (int o = 16; o; o >>= 1) v += __shfl_xor_sync(0xffffffffu, v, o);
    if ((t & 31) == 0) sh[t >> 5] = v;
    __syncthreads();
    if (t < 32) {
        int s = sh[t];
        #pragma unroll
        for (int o = 16; o; o >>= 1) s += __shfl_xor_sync(0xffffffffu, s, o);
        if (t == 0) g_bsum[b] = s;
    }
}

// block-local scan; warp 0 sums prior block-sums in parallel
__global__ void k_scan3() {
    __shared__ int wsum[32];
    __shared__ int sboff;
    int b = blockIdx.x, t = threadIdx.x;
    if (t < 32) {
        int acc = 0;
        for (int j = t; j < b; j += 32) acc += g_bsum[j];
        #pragma unroll
        for (int o = 16; o; o >>= 1) acc += __shfl_xor_sync(0xffffffffu, acc, o);
        if (t == 0) sboff = acc;
    }
    int i = b * SCAN_B + t;
    int v = (i < N_NODES) ? g_indeg[i] : 0;
    int xs = v;
    #pragma unroll
    for (int o = 1; o < 32; o <<= 1) {
        int y = __shfl_up_sync(0xffffffffu, xs, o);
        if ((t & 31) >= o) xs += y;
    }
    if ((t & 31) == 31) wsum[t >> 5] = xs;
    __syncthreads();
    if (t < 32) {
        int s = wsum[t];
        #pragma unroll
        for (int o = 1; o < 32; o <<= 1) {
            int y = __shfl_up_sync(0xffffffffu, s, o);
            if (t >= o) s += y;
        }
        wsum[t] = s;   // inclusive over warps
    }
    __syncthreads();
    int base = sboff + ((t >= 32) ? wsum[(t >> 5) - 1] : 0);
    int excl = base + xs - v;
    if (i < N_NODES) {
        g_off[i] = excl;
        g_cur[i] = excl;
        g_dinv[i] = rsqrtf((float)(v + 1));
    }
}

// -------- fused CSR fill (2 edges/thread, int2) + feature convert --------
// blocks [0, FILL_BLKS): fill; blocks [FILL_BLKS, FILL_BLKS+CVT_BLKS): cvt
#define E2 (N_EDGES/2)
#define FILL_BLKS ((E2 + 255)/256)           // 3125
#define CVT_BLKS  ((NQ + 255)/256)           // 12500

__global__ void k_fill_cvt(const int* __restrict__ ei, const float* __restrict__ x) {
    int b = blockIdx.x;
    if (b < FILL_BLKS) {
        int p = b * 256 + threadIdx.x;
        if (p >= E2) return;
        int2 s = ((const int2*)ei)[p];
        int2 d = ((const int2*)(ei + N_EDGES))[p];
        int pos0 = atomicAdd(&g_cur[d.x], 1);
        g_csr[pos0] = s.x;
        int pos1 = atomicAdd(&g_cur[d.y], 1);
        g_csr[pos1] = s.y;
    } else {
        int i = (b - FILL_BLKS) * 256 + threadIdx.x;
        if (i >= NQ) return;
        float dd = g_dinv[i >> 5];
        float4 t = ((const float4*)x)[i];
        t.x *= dd; t.y *= dd; t.z *= dd; t.w *= dd;
        g_h0[i] = f4_to_h4(t);
    }
}

// one warp per dst node; fp32 accum; 8-deep unrolled gather
__global__ void k_hop(int dir) {
    int w = (blockIdx.x * blockDim.x + threadIdx.x) >> 5;
    if (w >= N_NODES) return;
    int lane = threadIdx.x & 31;
    const uint2* in  = dir ? g_h1 : g_h0;
    uint2*       out = dir ? g_h0 : g_h1;
    int idx = w * 32 + lane;
    float4 acc = h4_to_f4(__ldg(&in[idx]));     // self loop
    int beg = g_off[w];
    int cnt = g_indeg[w];
    int i = 0;
    for (; i + 8 <= cnt; i += 8) {
        int s[8];
        #pragma unroll
        for (int j = 0; j < 8; j++) s[j] = __ldg(&g_csr[beg + i + j]);
        uint2 u[8];
        #pragma unroll
        for (int j = 0; j < 8; j++) u[j] = __ldg(&in[s[j] * 32 + lane]);
        #pragma unroll
        for (int j = 0; j < 8; j++) {
            float4 v = h4_to_f4(u[j]);
            acc.x += v.x; acc.y += v.y; acc.z += v.z; acc.w += v.w;
        }
    }
    for (; i < cnt; i++) {
        int s0 = __ldg(&g_csr[beg + i]);
        float4 v0 = h4_to_f4(__ldg(&in[s0 * 32 + lane]));
        acc.x += v0.x; acc.y += v0.y; acc.z += v0.z; acc.w += v0.w;
    }
    float d = g_dinv[w];
    float f = dir ? d : d * d;
    acc.x *= f; acc.y *= f; acc.z *= f; acc.w *= f;
    out[idx] = f4_to_h4(acc);
}

// -------- tensor-core GEMM + pool: z = relu(h2@W + b); pool += z --------
#define GM_NODES 64
#define SAS 136
#define SWS 136
#define SMEM_A_BYTES (GM_NODES*SAS*2)
#define SMEM_W_BYTES (FDIM*SWS*2)
#define GEMM_SMEM (SMEM_A_BYTES + SMEM_W_BYTES + GM_NODES*4)

__device__ __forceinline__ void mma16816(float4& d, unsigned a0, unsigned a1,
                                         unsigned a2, unsigned a3,
                                         unsigned b0, unsigned b1) {
    asm volatile("mma.sync.aligned.m16n8k16.row.col.f32.f16.f16.f32 "
        "{%0,%1,%2,%3}, {%4,%5,%6,%7}, {%8,%9}, {%0,%1,%2,%3};"
        : "+f"(d.x), "+f"(d.y), "+f"(d.z), "+f"(d.w)
        : "r"(a0), "r"(a1), "r"(a2), "r"(a3), "r"(b0), "r"(b1));
}

__global__ __launch_bounds__(128, 2) void k_gemm_pool(
        const float* __restrict__ bias, const int* __restrict__ batch) {
    extern __shared__ char smem[];
    __half* sA = (__half*)smem;                       // [64][SAS]
    __half* sW = (__half*)(smem + SMEM_A_BYTES);      // [128][SWS] (W^T: [n][k])
    float*  sO = (float*)smem;                        // overlay [64][128]
    int*    sB = (int*)(smem + SMEM_A_BYTES + SMEM_W_BYTES);
    int tid = threadIdx.x;
    int base = blockIdx.x * GM_NODES;

    for (int i = tid; i < GM_NODES*32; i += 128) {
        int r = i >> 5, q = i & 31;
        int node = base + r;
        uint2 u = make_uint2(0u, 0u);
        if (node < N_NODES) u = g_h0[node*32 + q];
        *(uint2*)&sA[r*SAS + q*4] = u;
    }
    for (int i = tid; i < FDIM*32; i += 128) {
        int r = i >> 5, q = i & 31;
        uint2 u = *(const uint2*)&g_Wh[r*FDIM + q*4];
        *(uint2*)&sW[r*SWS + q*4] = u;
    }
    if (tid < GM_NODES) {
        int node = base + tid;
        sB[tid] = (node < N_NODES) ? batch[node] : -1;
    }
    __syncthreads();

    int warp = tid >> 5, lane = tid & 31;
    int gid = lane >> 2, tig = lane & 3;
    int m0 = warp * 16;

    float4 acc[16];
    #pragma unroll
    for (int t = 0; t < 16; t++) acc[t] = make_float4(0.f, 0.f, 0.f, 0.f);

    #pragma unroll
    for (int k0 = 0; k0 < FDIM; k0 += 16) {
        unsigned a0 = *(unsigned*)&sA[(m0+gid)  *SAS + k0 + tig*2];
        unsigned a1 = *(unsigned*)&sA[(m0+gid+8)*SAS + k0 + tig*2];
        unsigned a2 = *(unsigned*)&sA[(m0+gid)  *SAS + k0 + tig*2 + 8];
        unsigned a3 = *(unsigned*)&sA[(m0+gid+8)*SAS + k0 + tig*2 + 8];
        #pragma unroll
        for (int t = 0; t < 16; t++) {
            int n0 = t * 8;
            unsigned b0 = *(unsigned*)&sW[(n0+gid)*SWS + k0 + tig*2];
            unsigned b1 = *(unsigned*)&sW[(n0+gid)*SWS + k0 + tig*2 + 8];
            mma16816(acc[t], a0, a1, a2, a3, b0, b1);
        }
    }

    __syncthreads();   // all A/W reads done before overlay writes
    #pragma unroll
    for (int t = 0; t < 16; t++) {
        int n0 = t * 8;
        sO[(m0+gid)  *FDIM + n0 + tig*2]     = acc[t].x;
        sO[(m0+gid)  *FDIM + n0 + tig*2 + 1] = acc[t].y;
        sO[(m0+gid+8)*FDIM + n0 + tig*2]     = acc[t].z;
        sO[(m0+gid+8)*FDIM + n0 + tig*2 + 1] = acc[t].w;
    }
    __syncwarp();      // each warp reads only its own 16 rows

    float4 bv = *(const float4*)&bias[lane*4];
    float4 run = make_float4(0.f, 0.f, 0.f, 0.f);
    int cur_gid = -1;
    #pragma unroll
    for (int n = 0; n < 16; n++) {
        int row = m0 + n;
        int gidn = sB[row];
        float4 a = *(float4*)&sO[row*FDIM + lane*4];
        float4 r;
        r.x = fmaxf(a.x + bv.x, 0.0f);
        r.y = fmaxf(a.y + bv.y, 0.0f);
        r.z = fmaxf(a.z + bv.z, 0.0f);
        r.w = fmaxf(a.w + bv.w, 0.0f);
        if (gidn != cur_gid) {
            if (cur_gid >= 0) {
                float* p = g_pool + cur_gid*FDIM + lane*4;
                atomicAdd(p+0, run.x); atomicAdd(p+1, run.y);
                atomicAdd(p+2, run.z); atomicAdd(p+3, run.w);
            }
            cur_gid = gidn;
            run = r;
        } else {
            run.x += r.x; run.y += r.y; run.z += r.z; run.w += r.w;
        }
    }
    if (cur_gid >= 0) {
        float* p = g_pool + cur_gid*FDIM + lane*4;
        atomicAdd(p+0, run.x); atomicAdd(p+1, run.y);
        atomicAdd(p+2, run.z); atomicAdd(p+3, run.w);
    }
}

// -------- mean + log_softmax, one block (128 threads) per graph --------
__global__ void k_softmax(float* __restrict__ out) {
    int g = blockIdx.x;
    int t = threadIdx.x;
    __shared__ float sm[4], ss[4];
    float c = fmaxf((float)g_cnt[g], 1.0f);
    float v = g_pool[g*FDIM + t] / c;
    float m = v;
    #pragma unroll
    for (int o = 16; o; o >>= 1) m = fmaxf(m, __shfl_xor_sync(0xffffffffu, m, o));
    if ((t & 31) == 0) sm[t >> 5] = m;
    __syncthreads();
    m = fmaxf(fmaxf(sm[0], sm[1]), fmaxf(sm[2], sm[3]));
    float e = expf(v - m);
    float s = e;
    #pragma unroll
    for (int o = 16; o; o >>= 1) s += __shfl_xor_sync(0xffffffffu, s, o);
    if ((t & 31) == 0) ss[t >> 5] = s;
    __syncthreads();
    s = ss[0] + ss[1] + ss[2] + ss[3];
    out[g*FDIM + t] = v - m - logf(s);
}

extern "C" void kernel_launch(void* const* d_in, const int* in_sizes, int n_in,
                              void* d_out, int out_size) {
    const float* x     = (const float*)d_in[0];
    const int*   ei    = (const int*)d_in[1];
    const int*   batch = (const int*)d_in[2];
    const float* Wm    = (const float*)d_in[3];
    const float* bias  = (const float*)d_in[4];
    float*       out   = (float*)d_out;

    cudaFuncSetAttribute(k_gemm_pool, cudaFuncAttributeMaxDynamicSharedMemorySize, GEMM_SMEM);

    k_init_wcvt  <<<(N_NODES + 255) / 256, 256>>>(Wm);
    k_degree_cnt <<<(N_EDGES + 255) / 256, 256>>>(ei, batch);
    k_scan1      <<<NBLK, SCAN_B>>>();
    k_scan3      <<<NBLK, SCAN_B>>>();
    k_fill_cvt   <<<FILL_BLKS + CVT_BLKS, 256>>>(ei, x);
    k_hop        <<<(N_NODES * 32 + 255) / 256, 256>>>(0);  // hop 1: h0 -> h1
    k_hop        <<<(N_NODES * 32 + 255) / 256, 256>>>(1);  // hop 2: h1 -> h0
    k_gemm_pool  <<<(N_NODES + GM_NODES - 1) / GM_NODES, 128, GEMM_SMEM>>>(bias, batch);
    k_softmax    <<<N_GRAPHS, FDIM>>>(out);
}

// round 12
// speedup vs baseline: 3.0324x; 1.0977x over previous
#include <cuda_runtime.h>
#include <cuda_fp16.h>

#define N_NODES 100000
#define N_EDGES 1600000
#define FDIM 128
#define N_GRAPHS 256
#define NODE_ELEMS (N_NODES*FDIM)
#define NQ (NODE_ELEMS/4)          // 4-feature packets per node grid (32/node)
#define SCAN_B 1024
#define NBLK ((N_NODES + SCAN_B - 1)/SCAN_B)   // 98

// -------- scratch (static device globals; no allocation anywhere) --------
__device__ int      g_indeg[N_NODES];
__device__ int      g_off[N_NODES];
__device__ int      g_cur[N_NODES];
__device__ int      g_csr[N_EDGES];
__device__ float    g_dinv[N_NODES];
__device__ int      g_bsum[NBLK];
__device__ unsigned g_q0[NQ];        // 12.8 MB e4m3 features (hop1 input)
__device__ unsigned g_q1[NQ];        // 12.8 MB e4m3 features (hop1 out, x16 scaled)
__device__ uint2    g_h0[NQ];        // 25.6 MB fp16 features (hop2 out -> GEMM)
__device__ __half   g_Wh[FDIM*FDIM]; // W^T in fp16: g_Wh[c*128+f] = W[f][c]
__device__ float    g_pool[N_GRAPHS*FDIM];
__device__ int      g_cnt[N_GRAPHS];

__device__ __forceinline__ uint2 f4_to_h4(float4 v) {
    __half2 a = __floats2half2_rn(v.x, v.y);
    __half2 b = __floats2half2_rn(v.z, v.w);
    uint2 u;
    u.x = *(unsigned*)&a;
    u.y = *(unsigned*)&b;
    return u;
}
// position-preserving fp8 pack/unpack (via f16x2, so byte order is consistent)
__device__ __forceinline__ unsigned pack_e4m3(float4 v) {
    __half2 a = __floats2half2_rn(v.x, v.y);
    __half2 b = __floats2half2_rn(v.z, v.w);
    unsigned short qa, qb;
    asm("cvt.rn.satfinite.e4m3x2.f16x2 %0, %1;" : "=h"(qa) : "r"(*(unsigned*)&a));
    asm("cvt.rn.satfinite.e4m3x2.f16x2 %0, %1;" : "=h"(qb) : "r"(*(unsigned*)&b));
    return (unsigned)qa | ((unsigned)qb << 16);
}
__device__ __forceinline__ void unpack_e4m3(unsigned q, __half2& a, __half2& b) {
    unsigned ra, rb;
    unsigned short lo = (unsigned short)(q & 0xFFFFu);
    unsigned short hi = (unsigned short)(q >> 16);
    asm("cvt.rn.f16x2.e4m3x2 %0, %1;" : "=r"(ra) : "h"(lo));
    asm("cvt.rn.f16x2.e4m3x2 %0, %1;" : "=r"(rb) : "h"(hi));
    a = *(__half2*)&ra;
    b = *(__half2*)&rb;
}

// -------- fused init + W convert --------
__global__ void k_init_wcvt(const float* __restrict__ Wm) {
    int i = blockIdx.x * blockDim.x + threadIdx.x;
    if (i < N_NODES) g_indeg[i] = 0;
    if (i < N_GRAPHS*FDIM) g_pool[i] = 0.0f;
    if (i < N_GRAPHS) g_cnt[i] = 0;
    if (i < FDIM*FDIM) {                 // W fp32 [f][c] -> fp16 transposed [c][f]
        int f = i >> 7, c = i & 127;
        g_Wh[c*FDIM + f] = __float2half(Wm[i]);
    }
}

// -------- degree histogram + per-graph node counts (folded) --------
__global__ void k_degree_cnt(const int* __restrict__ ei, const int* __restrict__ batch) {
    int e = blockIdx.x * blockDim.x + threadIdx.x;
    if (e < N_EDGES) atomicAdd(&g_indeg[ei[N_EDGES + e]], 1);
    if (e < N_NODES) atomicAdd(&g_cnt[batch[e]], 1);
}

// -------- 2-phase coalesced exclusive scan of indegrees --------
__global__ void k_scan1() {
    __shared__ int sh[32];
    int b = blockIdx.x, t = threadIdx.x;
    int i = b * SCAN_B + t;
    int v = (i < N_NODES) ? g_indeg[i] : 0;
    #pragma unroll
    for (int o = 16; o; o >>= 1) v += __shfl_xor_sync(0xffffffffu, v, o);
    if ((t & 31) == 0) sh[t >> 5] = v;
    __syncthreads();
    if (t < 32) {
        int s = sh[t];
        #pragma unroll
        for (int o = 16; o; o >>= 1) s += __shfl_xor_sync(0xffffffffu, s, o);
        if (t == 0) g_bsum[b] = s;
    }
}

// block-local scan; warp 0 sums prior block-sums in parallel
__global__ void k_scan3() {
    __shared__ int wsum[32];
    __shared__ int sboff;
    int b = blockIdx.x, t = threadIdx.x;
    if (t < 32) {
        int acc = 0;
        for (int j = t; j < b; j += 32) acc += g_bsum[j];
        #pragma unroll
        for (int o = 16; o; o >>= 1) acc += __shfl_xor_sync(0xffffffffu, acc, o);
        if (t == 0) sboff = acc;
    }
    int i = b * SCAN_B + t;
    int v = (i < N_NODES) ? g_indeg[i] : 0;
    int xs = v;
    #pragma unroll
    for (int o = 1; o < 32; o <<= 1) {
        int y = __shfl_up_sync(0xffffffffu, xs, o);
        if ((t & 31) >= o) xs += y;
    }
    if ((t & 31) == 31) wsum[t >> 5] = xs;
    __syncthreads();
    if (t < 32) {
        int s = wsum[t];
        #pragma unroll
        for (int o = 1; o < 32; o <<= 1) {
            int y = __shfl_up_sync(0xffffffffu, s, o);
            if (t >= o) s += y;
        }
        wsum[t] = s;   // inclusive over warps
    }
    __syncthreads();
    int base = sboff + ((t >= 32) ? wsum[(t >> 5) - 1] : 0);
    int excl = base + xs - v;
    if (i < N_NODES) {
        g_off[i] = excl;
        g_cur[i] = excl;
        g_dinv[i] = rsqrtf((float)(v + 1));
    }
}

// -------- fused CSR fill (2 edges/thread, int2) + fp8 feature convert --------
#define E2 (N_EDGES/2)
#define FILL_BLKS ((E2 + 255)/256)           // 3125
#define CVT_BLKS  ((NQ + 255)/256)           // 12500

__global__ void k_fill_cvt(const int* __restrict__ ei, const float* __restrict__ x) {
    int b = blockIdx.x;
    if (b < FILL_BLKS) {
        int p = b * 256 + threadIdx.x;
        if (p >= E2) return;
        int2 s = ((const int2*)ei)[p];
        int2 d = ((const int2*)(ei + N_EDGES))[p];
        int pos0 = atomicAdd(&g_cur[d.x], 1);
        g_csr[pos0] = s.x;
        int pos1 = atomicAdd(&g_cur[d.y], 1);
        g_csr[pos1] = s.y;
    } else {
        int i = (b - FILL_BLKS) * 256 + threadIdx.x;
        if (i >= NQ) return;
        float dd = g_dinv[i >> 5];
        float4 t = ((const float4*)x)[i];
        t.x *= dd; t.y *= dd; t.z *= dd; t.w *= dd;
        g_q0[i] = pack_e4m3(t);          // g0 = e4m3(dinv * x)
    }
}

// shared gather core: fp8 rows, fp16 pair accumulation, 8-deep unroll
__device__ __forceinline__ float4 hop_gather(const unsigned* __restrict__ in,
                                             int w, int lane) {
    __half2 acc0, acc1;
    unpack_e4m3(__ldg(&in[w * 32 + lane]), acc0, acc1);   // self loop
    int beg = g_off[w];
    int cnt = g_indeg[w];
    int i = 0;
    for (; i + 8 <= cnt; i += 8) {
        int s[8];
        #pragma unroll
        for (int j = 0; j < 8; j++) s[j] = __ldg(&g_csr[beg + i + j]);
        unsigned u[8];
        #pragma unroll
        for (int j = 0; j < 8; j++) u[j] = __ldg(&in[s[j] * 32 + lane]);
        #pragma unroll
        for (int j = 0; j < 8; j++) {
            __half2 a, c;
            unpack_e4m3(u[j], a, c);
            acc0 = __hadd2(acc0, a);
            acc1 = __hadd2(acc1, c);
        }
    }
    for (; i < cnt; i++) {
        int s0 = __ldg(&g_csr[beg + i]);
        __half2 a, c;
        unpack_e4m3(__ldg(&in[s0 * 32 + lane]), a, c);
        acc0 = __hadd2(acc0, a);
        acc1 = __hadd2(acc1, c);
    }
    float2 f0 = __half22float2(acc0);
    float2 f1 = __half22float2(acc1);
    return make_float4(f0.x, f0.y, f1.x, f1.y);
}

// hop1: q0 -> q1, store 16*dinv^2*(sum+self)  (x16 centers e4m3 range)
__global__ void k_hop1() {
    int w = (blockIdx.x * blockDim.x + threadIdx.x) >> 5;
    if (w >= N_NODES) return;
    int lane = threadIdx.x & 31;
    float4 acc = hop_gather(g_q0, w, lane);
    float d = g_dinv[w];
    float f = d * d * 16.0f;
    acc.x *= f; acc.y *= f; acc.z *= f; acc.w *= f;
    g_q1[w * 32 + lane] = pack_e4m3(acc);
}

// hop2: q1 -> h0 (fp16), store (dinv/16)*(sum+self)
__global__ void k_hop2() {
    int w = (blockIdx.x * blockDim.x + threadIdx.x) >> 5;
    if (w >= N_NODES) return;
    int lane = threadIdx.x & 31;
    float4 acc = hop_gather(g_q1, w, lane);
    float f = g_dinv[w] * 0.0625f;
    acc.x *= f; acc.y *= f; acc.z *= f; acc.w *= f;
    g_h0[w * 32 + lane] = f4_to_h4(acc);
}

// -------- tensor-core GEMM + pool: z = relu(h2@W + b); pool += z --------
#define GM_NODES 64
#define SAS 136
#define SWS 136
#define SMEM_A_BYTES (GM_NODES*SAS*2)
#define SMEM_W_BYTES (FDIM*SWS*2)
#define GEMM_SMEM (SMEM_A_BYTES + SMEM_W_BYTES + GM_NODES*4)

__device__ __forceinline__ void mma16816(float4& d, unsigned a0, unsigned a1,
                                         unsigned a2, unsigned a3,
                                         unsigned b0, unsigned b1) {
    asm volatile("mma.sync.aligned.m16n8k16.row.col.f32.f16.f16.f32 "
        "{%0,%1,%2,%3}, {%4,%5,%6,%7}, {%8,%9}, {%0,%1,%2,%3};"
        : "+f"(d.x), "+f"(d.y), "+f"(d.z), "+f"(d.w)
        : "r"(a0), "r"(a1), "r"(a2), "r"(a3), "r"(b0), "r"(b1));
}

__global__ __launch_bounds__(128, 2) void k_gemm_pool(
        const float* __restrict__ bias, const int* __restrict__ batch) {
    extern __shared__ char smem[];
    __half* sA = (__half*)smem;                       // [64][SAS]
    __half* sW = (__half*)(smem + SMEM_A_BYTES);      // [128][SWS] (W^T: [n][k])
    float*  sO = (float*)smem;                        // overlay [64][128]
    int*    sB = (int*)(smem + SMEM_A_BYTES + SMEM_W_BYTES);
    int tid = threadIdx.x;
    int base = blockIdx.x * GM_NODES;

    for (int i = tid; i < GM_NODES*32; i += 128) {
        int r = i >> 5, q = i & 31;
        int node = base + r;
        uint2 u = make_uint2(0u, 0u);
        if (node < N_NODES) u = g_h0[node*32 + q];
        *(uint2*)&sA[r*SAS + q*4] = u;
    }
    for (int i = tid; i < FDIM*32; i += 128) {
        int r = i >> 5, q = i & 31;
        uint2 u = *(const uint2*)&g_Wh[r*FDIM + q*4];
        *(uint2*)&sW[r*SWS + q*4] = u;
    }
    if (tid < GM_NODES) {
        int node = base + tid;
        sB[tid] = (node < N_NODES) ? batch[node] : -1;
    }
    __syncthreads();

    int warp = tid >> 5, lane = tid & 31;
    int gid = lane >> 2, tig = lane & 3;
    int m0 = warp * 16;

    float4 acc[16];
    #pragma unroll
    for (int t = 0; t < 16; t++) acc[t] = make_float4(0.f, 0.f, 0.f, 0.f);

    #pragma unroll
    for (int k0 = 0; k0 < FDIM; k0 += 16) {
        unsigned a0 = *(unsigned*)&sA[(m0+gid)  *SAS + k0 + tig*2];
        unsigned a1 = *(unsigned*)&sA[(m0+gid+8)*SAS + k0 + tig*2];
        unsigned a2 = *(unsigned*)&sA[(m0+gid)  *SAS + k0 + tig*2 + 8];
        unsigned a3 = *(unsigned*)&sA[(m0+gid+8)*SAS + k0 + tig*2 + 8];
        #pragma unroll
        for (int t = 0; t < 16; t++) {
            int n0 = t * 8;
            unsigned b0 = *(unsigned*)&sW[(n0+gid)*SWS + k0 + tig*2];
            unsigned b1 = *(unsigned*)&sW[(n0+gid)*SWS + k0 + tig*2 + 8];
            mma16816(acc[t], a0, a1, a2, a3, b0, b1);
        }
    }

    __syncthreads();   // all A/W reads done before overlay writes
    #pragma unroll
    for (int t = 0; t < 16; t++) {
        int n0 = t * 8;
        sO[(m0+gid)  *FDIM + n0 + tig*2]     = acc[t].x;
        sO[(m0+gid)  *FDIM + n0 + tig*2 + 1] = acc[t].y;
        sO[(m0+gid+8)*FDIM + n0 + tig*2]     = acc[t].z;
        sO[(m0+gid+8)*FDIM + n0 + tig*2 + 1] = acc[t].w;
    }
    __syncwarp();      // each warp reads only its own 16 rows

    float4 bv = *(const float4*)&bias[lane*4];
    float4 run = make_float4(0.f, 0.f, 0.f, 0.f);
    int cur_gid = -1;
    #pragma unroll
    for (int n = 0; n < 16; n++) {
        int row = m0 + n;
        int gidn = sB[row];
        float4 a = *(float4*)&sO[row*FDIM + lane*4];
        float4 r;
        r.x = fmaxf(a.x + bv.x, 0.0f);
        r.y = fmaxf(a.y + bv.y, 0.0f);
        r.z = fmaxf(a.z + bv.z, 0.0f);
        r.w = fmaxf(a.w + bv.w, 0.0f);
        if (gidn != cur_gid) {
            if (cur_gid >= 0) {
                float* p = g_pool + cur_gid*FDIM + lane*4;
                atomicAdd(p+0, run.x); atomicAdd(p+1, run.y);
                atomicAdd(p+2, run.z); atomicAdd(p+3, run.w);
            }
            cur_gid = gidn;
            run = r;
        } else {
            run.x += r.x; run.y += r.y; run.z += r.z; run.w += r.w;
        }
    }
    if (cur_gid >= 0) {
        float* p = g_pool + cur_gid*FDIM + lane*4;
        atomicAdd(p+0, run.x); atomicAdd(p+1, run.y);
        atomicAdd(p+2, run.z); atomicAdd(p+3, run.w);
    }
}

// -------- mean + log_softmax, one block (128 threads) per graph --------
__global__ void k_softmax(float* __restrict__ out) {
    int g = blockIdx.x;
    int t = threadIdx.x;
    __shared__ float sm[4], ss[4];
    float c = fmaxf((float)g_cnt[g], 1.0f);
    float v = g_pool[g*FDIM + t] / c;
    float m = v;
    #pragma unroll
    for (int o = 16; o; o >>= 1) m = fmaxf(m, __shfl_xor_sync(0xffffffffu, m, o));
    if ((t & 31) == 0) sm[t >> 5] = m;
    __syncthreads();
    m = fmaxf(fmaxf(sm[0], sm[1]), fmaxf(sm[2], sm[3]));
    float e = expf(v - m);
    float s = e;
    #pragma unroll
    for (int o = 16; o; o >>= 1) s += __shfl_xor_sync(0xffffffffu, s, o);
    if ((t & 31) == 0) ss[t >> 5] = s;
    __syncthreads();
    s = ss[0] + ss[1] + ss[2] + ss[3];
    out[g*FDIM + t] = v - m - logf(s);
}

extern "C" void kernel_launch(void* const* d_in, const int* in_sizes, int n_in,
                              void* d_out, int out_size) {
    const float* x     = (const float*)d_in[0];
    const int*   ei    = (const int*)d_in[1];
    const int*   batch = (const int*)d_in[2];
    const float* Wm    = (const float*)d_in[3];
    const float* bias  = (const float*)d_in[4];
    float*       out   = (float*)d_out;

    cudaFuncSetAttribute(k_gemm_pool, cudaFuncAttributeMaxDynamicSharedMemorySize, GEMM_SMEM);

    k_init_wcvt  <<<(N_NODES + 255) / 256, 256>>>(Wm);
    k_degree_cnt <<<(N_EDGES + 255) / 256, 256>>>(ei, batch);
    k_scan1      <<<NBLK, SCAN_B>>>();
    k_scan3      <<<NBLK, SCAN_B>>>();
    k_fill_cvt   <<<FILL_BLKS + CVT_BLKS, 256>>>(ei, x);
    k_hop1       <<<(N_NODES * 32 + 255) / 256, 256>>>();  // q0 -> q1 (fp8)
    k_hop2       <<<(N_NODES * 32 + 255) / 256, 256>>>();  // q1 -> h0 (fp16)
    k_gemm_pool  <<<(N_NODES + GM_NODES - 1) / GM_NODES, 128, GEMM_SMEM>>>(bias, batch);
    k_softmax    <<<N_GRAPHS, FDIM>>>(out);
}